// round 3
// baseline (speedup 1.0000x reference)
#include <cuda_runtime.h>
#include <cuda_fp16.h>

#define D       128
#define NMAX    50000

#define BM 128
#define BK 32
#define SST 136   // smem row stride (floats): 136 mod 32 = 8 -> 8t+g conflict-free frags

// Scratch: pre-transformed, pre-scaled per-relation node features in fp16.
__device__ __half g_hrel[2ull * NMAX * D];

static __device__ __forceinline__ unsigned f2tf(float x) {
    unsigned r;
    asm("cvt.rna.tf32.f32 %0, %1;" : "=r"(r) : "f"(x));
    return r;
}

static __device__ __forceinline__ void mma_tf32(
    float c[4], unsigned a0, unsigned a1, unsigned a2, unsigned a3,
    unsigned b0, unsigned b1)
{
    asm volatile(
        "mma.sync.aligned.m16n8k8.row.col.f32.tf32.tf32.f32 "
        "{%0,%1,%2,%3}, {%4,%5,%6,%7}, {%8,%9}, {%0,%1,%2,%3};"
        : "+f"(c[0]), "+f"(c[1]), "+f"(c[2]), "+f"(c[3])
        : "r"(a0), "r"(a1), "r"(a2), "r"(a3), "r"(b0), "r"(b1));
}

// Tensor-core GEMM, weight scaling fused into the B-tile load:
//   cb 0,1: h_rel[cb] = feat @ (s*W[cb])      (fp16 output)
//   cb 2:   out      = bias + feat @ (s*loopW) (fp32 output)
__global__ __launch_bounds__(256, 2) void gemm_tc(
    const float* __restrict__ feat,
    const float* __restrict__ weight,
    const float* __restrict__ loopw,
    const float* __restrict__ bias,
    float* __restrict__ out,
    int N)
{
    __shared__ float As[2][BK][SST];  // [buf][k][m], tf32 bits
    __shared__ float Bs[2][BK][SST];  // [buf][k][n], tf32 bits

    const int tid  = threadIdx.x;
    const int lane = tid & 31;
    const int wid  = tid >> 5;
    const int g    = lane >> 2;       // 0..7
    const int t    = lane & 3;        // 0..3
    const int wm   = (wid & 3) * 32;
    const int wn   = (wid >> 2) * 64;
    const int m0   = blockIdx.x * BM;
    const int cb   = blockIdx.y;      // 0,1: h_rel ; 2: out/loop

    const float s = 0.70710678118654752440f;
    const float* B = (cb < 2) ? (weight + (size_t)cb * D * D) : loopw;

    const int arow = tid >> 1;        // 0..127 (A tile row)
    const int gm_a = m0 + arow;

    float acc[2][8][4];
#pragma unroll
    for (int i = 0; i < 2; i++)
#pragma unroll
        for (int j = 0; j < 8; j++)
#pragma unroll
            for (int q = 0; q < 4; q++) acc[i][j][q] = 0.f;

    float4 ra[4];     // staged A (4 float4 per thread)
    float4 rb[4];     // staged B (4 float4 per thread)

    // ---- prologue: load panel 0
#pragma unroll
    for (int i = 0; i < 4; i++) {
        int c = (tid & 1) * 4 + i;
        ra[i] = make_float4(0.f, 0.f, 0.f, 0.f);
        if (gm_a < N) ra[i] = *(const float4*)&feat[(size_t)gm_a * D + c * 4];
    }
#pragma unroll
    for (int tt = 0; tt < 4; tt++) {
        int linear = tid + tt * 256;
        int row = linear >> 5;
        int c   = linear & 31;
        rb[tt] = *(const float4*)&B[(size_t)row * D + c * 4];
    }

    int buf = 0;
    // store panel 0
#pragma unroll
    for (int i = 0; i < 4; i++) {
        int c = (tid & 1) * 4 + i;
        As[0][c * 4 + 0][arow] = __uint_as_float(f2tf(ra[i].x));
        As[0][c * 4 + 1][arow] = __uint_as_float(f2tf(ra[i].y));
        As[0][c * 4 + 2][arow] = __uint_as_float(f2tf(ra[i].z));
        As[0][c * 4 + 3][arow] = __uint_as_float(f2tf(ra[i].w));
    }
#pragma unroll
    for (int tt = 0; tt < 4; tt++) {
        int linear = tid + tt * 256;
        int row = linear >> 5;
        int c   = linear & 31;
        float4 w;
        w.x = __uint_as_float(f2tf(s * rb[tt].x));
        w.y = __uint_as_float(f2tf(s * rb[tt].y));
        w.z = __uint_as_float(f2tf(s * rb[tt].z));
        w.w = __uint_as_float(f2tf(s * rb[tt].w));
        *(float4*)&Bs[0][row][c * 4] = w;
    }
    __syncthreads();

#pragma unroll
    for (int p = 0; p < 4; p++) {
        int k_next = (p + 1) * BK;
        // prefetch next panel into registers (overlaps with mma below)
        if (p < 3) {
#pragma unroll
            for (int i = 0; i < 4; i++) {
                int c = (tid & 1) * 4 + i;
                ra[i] = make_float4(0.f, 0.f, 0.f, 0.f);
                if (gm_a < N) ra[i] = *(const float4*)&feat[(size_t)gm_a * D + k_next + c * 4];
            }
#pragma unroll
            for (int tt = 0; tt < 4; tt++) {
                int linear = tid + tt * 256;
                int row = linear >> 5;
                int c   = linear & 31;
                rb[tt] = *(const float4*)&B[(size_t)(k_next + row) * D + c * 4];
            }
        }

        // mma on current buffer
#pragma unroll
        for (int kk = 0; kk < BK; kk += 8) {
            unsigned a[2][4];
#pragma unroll
            for (int mt = 0; mt < 2; mt++) {
                int mb = wm + mt * 16;
                a[mt][0] = __float_as_uint(As[buf][kk + t]    [mb + g]);
                a[mt][1] = __float_as_uint(As[buf][kk + t]    [mb + g + 8]);
                a[mt][2] = __float_as_uint(As[buf][kk + t + 4][mb + g]);
                a[mt][3] = __float_as_uint(As[buf][kk + t + 4][mb + g + 8]);
            }
#pragma unroll
            for (int nt = 0; nt < 8; nt++) {
                int nb = wn + nt * 8;
                unsigned b0 = __float_as_uint(Bs[buf][kk + t]    [nb + g]);
                unsigned b1 = __float_as_uint(Bs[buf][kk + t + 4][nb + g]);
                mma_tf32(acc[0][nt], a[0][0], a[0][1], a[0][2], a[0][3], b0, b1);
                mma_tf32(acc[1][nt], a[1][0], a[1][1], a[1][2], a[1][3], b0, b1);
            }
        }

        if (p < 3) {
            int nb2 = buf ^ 1;
#pragma unroll
            for (int i = 0; i < 4; i++) {
                int c = (tid & 1) * 4 + i;
                As[nb2][c * 4 + 0][arow] = __uint_as_float(f2tf(ra[i].x));
                As[nb2][c * 4 + 1][arow] = __uint_as_float(f2tf(ra[i].y));
                As[nb2][c * 4 + 2][arow] = __uint_as_float(f2tf(ra[i].z));
                As[nb2][c * 4 + 3][arow] = __uint_as_float(f2tf(ra[i].w));
            }
#pragma unroll
            for (int tt = 0; tt < 4; tt++) {
                int linear = tid + tt * 256;
                int row = linear >> 5;
                int c   = linear & 31;
                float4 w;
                w.x = __uint_as_float(f2tf(s * rb[tt].x));
                w.y = __uint_as_float(f2tf(s * rb[tt].y));
                w.z = __uint_as_float(f2tf(s * rb[tt].z));
                w.w = __uint_as_float(f2tf(s * rb[tt].w));
                *(float4*)&Bs[nb2][row][c * 4] = w;
            }
            __syncthreads();
            buf ^= 1;
        }
    }

    // ---- Epilogue: frag (c0,c1)@(g,2t), (c2,c3)@(g+8,2t)
#pragma unroll
    for (int mt = 0; mt < 2; mt++) {
        int gm_lo = m0 + wm + mt * 16 + g;
        int gm_hi = gm_lo + 8;
#pragma unroll
        for (int nt = 0; nt < 8; nt++) {
            int col = wn + nt * 8 + 2 * t;
            if (cb < 2) {
                __half* dstb = &g_hrel[(size_t)cb * N * D];
                if (gm_lo < N)
                    *(__half2*)&dstb[(size_t)gm_lo * D + col] =
                        __floats2half2_rn(acc[mt][nt][0], acc[mt][nt][1]);
                if (gm_hi < N)
                    *(__half2*)&dstb[(size_t)gm_hi * D + col] =
                        __floats2half2_rn(acc[mt][nt][2], acc[mt][nt][3]);
            } else {
                float2 bv = *(const float2*)&bias[col];
                if (gm_lo < N)
                    *(float2*)&out[(size_t)gm_lo * D + col] =
                        make_float2(acc[mt][nt][0] + bv.x, acc[mt][nt][1] + bv.y);
                if (gm_hi < N)
                    *(float2*)&out[(size_t)gm_hi * D + col] =
                        make_float2(acc[mt][nt][2] + bv.x, acc[mt][nt][3] + bv.y);
            }
        }
    }
}

// One warp per edge: gather fp16 transformed src row, vector-atomicAdd fp32
// into the dst row.
__global__ __launch_bounds__(256) void edge_scatter(
    const int* __restrict__ src,
    const int* __restrict__ dst,
    const int* __restrict__ et,
    float* __restrict__ out,
    int E, int N)
{
    int gw = (blockIdx.x * 256 + threadIdx.x) >> 5;
    if (gw >= E) return;
    int lane = threadIdx.x & 31;
    int s = __ldg(&src[gw]);
    int d = __ldg(&dst[gw]);
    int r = __ldg(&et[gw]);
    const __half2* row = (const __half2*)&g_hrel[((size_t)r * N + (size_t)s) * D];
    __half2 h0 = row[lane * 2];
    __half2 h1 = row[lane * 2 + 1];
    float2 f0 = __half22float2(h0);
    float2 f1 = __half22float2(h1);
    atomicAdd((float4*)&out[(size_t)d * D + lane * 4],
              make_float4(f0.x, f0.y, f1.x, f1.y));
}

extern "C" void kernel_launch(void* const* d_in, const int* in_sizes, int n_in,
                              void* d_out, int out_size) {
    const float* feat   = (const float*)d_in[0];
    const int*   src    = (const int*)d_in[1];
    const int*   dst    = (const int*)d_in[2];
    const int*   etypes = (const int*)d_in[3];
    const float* weight = (const float*)d_in[4];
    const float* loopw  = (const float*)d_in[5];
    const float* bias   = (const float*)d_in[6];
    float* out = (float*)d_out;

    int N = in_sizes[0] / D;
    int E = in_sizes[1];

    dim3 grid((N + BM - 1) / BM, 3);
    gemm_tc<<<grid, 256>>>(feat, weight, loopw, bias, out, N);

    int nwarp_blocks = (E * 32 + 255) / 256;
    edge_scatter<<<nwarp_blocks, 256>>>(src, dst, etypes, out, E, N);
}

// round 4
// speedup vs baseline: 1.3453x; 1.3453x over previous
#include <cuda_runtime.h>
#include <cuda_fp16.h>

#define D       128
#define NMAX    50000
#define CAP     64

#define BM 128
#define BK 32
#define SST 136   // smem row stride (floats): 136 mod 32 = 8 -> conflict-free frags

// Scratch: pre-transformed pre-scaled per-relation node features (fp16),
// per-node edge counters, and fixed-capacity edge buckets.
__device__ __half   g_hrel[2ull * NMAX * D];
__device__ int      g_cnt[NMAX];
__device__ unsigned g_bucket[(size_t)NMAX * CAP];

static __device__ __forceinline__ unsigned f2tf(float x) {
    unsigned r;
    asm("cvt.rna.tf32.f32 %0, %1;" : "=r"(r) : "f"(x));
    return r;
}

static __device__ __forceinline__ void mma_tf32(
    float c[4], unsigned a0, unsigned a1, unsigned a2, unsigned a3,
    unsigned b0, unsigned b1)
{
    asm volatile(
        "mma.sync.aligned.m16n8k8.row.col.f32.tf32.tf32.f32 "
        "{%0,%1,%2,%3}, {%4,%5,%6,%7}, {%8,%9}, {%0,%1,%2,%3};"
        : "+f"(c[0]), "+f"(c[1]), "+f"(c[2]), "+f"(c[3])
        : "r"(a0), "r"(a1), "r"(a2), "r"(a3), "r"(b0), "r"(b1));
}

// Tensor-core GEMM, weight scaling fused into the B-tile load:
//   cb 0,1: h_rel[cb] = feat @ (s*W[cb])       (fp16 output)
//   cb 2:   out      = bias + feat @ (s*loopW) (fp32 output)
// cb==0 blocks also zero the per-node counters for the binning pass.
__global__ __launch_bounds__(256, 2) void gemm_tc(
    const float* __restrict__ feat,
    const float* __restrict__ weight,
    const float* __restrict__ loopw,
    const float* __restrict__ bias,
    float* __restrict__ out,
    int N)
{
    __shared__ float As[2][BK][SST];
    __shared__ float Bs[2][BK][SST];

    const int tid  = threadIdx.x;
    const int lane = tid & 31;
    const int wid  = tid >> 5;
    const int g    = lane >> 2;
    const int t    = lane & 3;
    const int wm   = (wid & 3) * 32;
    const int wn   = (wid >> 2) * 64;
    const int m0   = blockIdx.x * BM;
    const int cb   = blockIdx.y;

    if (cb == 0 && tid < BM) {
        int n = m0 + tid;
        if (n < N) g_cnt[n] = 0;
    }

    const float s = 0.70710678118654752440f;
    const float* B = (cb < 2) ? (weight + (size_t)cb * D * D) : loopw;

    const int arow = tid >> 1;
    const int gm_a = m0 + arow;

    float acc[2][8][4];
#pragma unroll
    for (int i = 0; i < 2; i++)
#pragma unroll
        for (int j = 0; j < 8; j++)
#pragma unroll
            for (int q = 0; q < 4; q++) acc[i][j][q] = 0.f;

    float4 ra[4];
    float4 rb[4];

#pragma unroll
    for (int i = 0; i < 4; i++) {
        int c = (tid & 1) * 4 + i;
        ra[i] = make_float4(0.f, 0.f, 0.f, 0.f);
        if (gm_a < N) ra[i] = *(const float4*)&feat[(size_t)gm_a * D + c * 4];
    }
#pragma unroll
    for (int tt = 0; tt < 4; tt++) {
        int linear = tid + tt * 256;
        int row = linear >> 5;
        int c   = linear & 31;
        rb[tt] = *(const float4*)&B[(size_t)row * D + c * 4];
    }

    int buf = 0;
#pragma unroll
    for (int i = 0; i < 4; i++) {
        int c = (tid & 1) * 4 + i;
        As[0][c * 4 + 0][arow] = __uint_as_float(f2tf(ra[i].x));
        As[0][c * 4 + 1][arow] = __uint_as_float(f2tf(ra[i].y));
        As[0][c * 4 + 2][arow] = __uint_as_float(f2tf(ra[i].z));
        As[0][c * 4 + 3][arow] = __uint_as_float(f2tf(ra[i].w));
    }
#pragma unroll
    for (int tt = 0; tt < 4; tt++) {
        int linear = tid + tt * 256;
        int row = linear >> 5;
        int c   = linear & 31;
        float4 w;
        w.x = __uint_as_float(f2tf(s * rb[tt].x));
        w.y = __uint_as_float(f2tf(s * rb[tt].y));
        w.z = __uint_as_float(f2tf(s * rb[tt].z));
        w.w = __uint_as_float(f2tf(s * rb[tt].w));
        *(float4*)&Bs[0][row][c * 4] = w;
    }
    __syncthreads();

#pragma unroll
    for (int p = 0; p < 4; p++) {
        int k_next = (p + 1) * BK;
        if (p < 3) {
#pragma unroll
            for (int i = 0; i < 4; i++) {
                int c = (tid & 1) * 4 + i;
                ra[i] = make_float4(0.f, 0.f, 0.f, 0.f);
                if (gm_a < N) ra[i] = *(const float4*)&feat[(size_t)gm_a * D + k_next + c * 4];
            }
#pragma unroll
            for (int tt = 0; tt < 4; tt++) {
                int linear = tid + tt * 256;
                int row = linear >> 5;
                int c   = linear & 31;
                rb[tt] = *(const float4*)&B[(size_t)(k_next + row) * D + c * 4];
            }
        }

#pragma unroll
        for (int kk = 0; kk < BK; kk += 8) {
            unsigned a[2][4];
#pragma unroll
            for (int mt = 0; mt < 2; mt++) {
                int mb = wm + mt * 16;
                a[mt][0] = __float_as_uint(As[buf][kk + t]    [mb + g]);
                a[mt][1] = __float_as_uint(As[buf][kk + t]    [mb + g + 8]);
                a[mt][2] = __float_as_uint(As[buf][kk + t + 4][mb + g]);
                a[mt][3] = __float_as_uint(As[buf][kk + t + 4][mb + g + 8]);
            }
#pragma unroll
            for (int nt = 0; nt < 8; nt++) {
                int nb = wn + nt * 8;
                unsigned b0 = __float_as_uint(Bs[buf][kk + t]    [nb + g]);
                unsigned b1 = __float_as_uint(Bs[buf][kk + t + 4][nb + g]);
                mma_tf32(acc[0][nt], a[0][0], a[0][1], a[0][2], a[0][3], b0, b1);
                mma_tf32(acc[1][nt], a[1][0], a[1][1], a[1][2], a[1][3], b0, b1);
            }
        }

        if (p < 3) {
            int nb2 = buf ^ 1;
#pragma unroll
            for (int i = 0; i < 4; i++) {
                int c = (tid & 1) * 4 + i;
                As[nb2][c * 4 + 0][arow] = __uint_as_float(f2tf(ra[i].x));
                As[nb2][c * 4 + 1][arow] = __uint_as_float(f2tf(ra[i].y));
                As[nb2][c * 4 + 2][arow] = __uint_as_float(f2tf(ra[i].z));
                As[nb2][c * 4 + 3][arow] = __uint_as_float(f2tf(ra[i].w));
            }
#pragma unroll
            for (int tt = 0; tt < 4; tt++) {
                int linear = tid + tt * 256;
                int row = linear >> 5;
                int c   = linear & 31;
                float4 w;
                w.x = __uint_as_float(f2tf(s * rb[tt].x));
                w.y = __uint_as_float(f2tf(s * rb[tt].y));
                w.z = __uint_as_float(f2tf(s * rb[tt].z));
                w.w = __uint_as_float(f2tf(s * rb[tt].w));
                *(float4*)&Bs[nb2][row][c * 4] = w;
            }
            __syncthreads();
            buf ^= 1;
        }
    }

#pragma unroll
    for (int mt = 0; mt < 2; mt++) {
        int gm_lo = m0 + wm + mt * 16 + g;
        int gm_hi = gm_lo + 8;
#pragma unroll
        for (int nt = 0; nt < 8; nt++) {
            int col = wn + nt * 8 + 2 * t;
            if (cb < 2) {
                __half* dstb = &g_hrel[(size_t)cb * N * D];
                if (gm_lo < N)
                    *(__half2*)&dstb[(size_t)gm_lo * D + col] =
                        __floats2half2_rn(acc[mt][nt][0], acc[mt][nt][1]);
                if (gm_hi < N)
                    *(__half2*)&dstb[(size_t)gm_hi * D + col] =
                        __floats2half2_rn(acc[mt][nt][2], acc[mt][nt][3]);
            } else {
                float2 bv = *(const float2*)&bias[col];
                if (gm_lo < N)
                    *(float2*)&out[(size_t)gm_lo * D + col] =
                        make_float2(acc[mt][nt][0] + bv.x, acc[mt][nt][1] + bv.y);
                if (gm_hi < N)
                    *(float2*)&out[(size_t)gm_hi * D + col] =
                        make_float2(acc[mt][nt][2] + bv.x, acc[mt][nt][3] + bv.y);
            }
        }
    }
}

// One thread per edge: append packed (rel<<24 | src) into dst's bucket.
// Overflow (probabilistically impossible at deg~Poisson(10), CAP=64) falls
// back to direct atomic accumulation, preserving correctness.
__global__ __launch_bounds__(256) void bin_edges(
    const int* __restrict__ src,
    const int* __restrict__ dst,
    const int* __restrict__ et,
    float* __restrict__ out,
    int E, int N)
{
    int e = blockIdx.x * blockDim.x + threadIdx.x;
    if (e >= E) return;
    int s = __ldg(&src[e]);
    int d = __ldg(&dst[e]);
    int r = __ldg(&et[e]);
    int pos = atomicAdd(&g_cnt[d], 1);
    if (pos < CAP) {
        g_bucket[(size_t)d * CAP + pos] = (unsigned)s | ((unsigned)r << 24);
    } else {
        const __half* row = &g_hrel[((size_t)r * N + (size_t)s) * D];
        for (int i = 0; i < D; i++)
            atomicAdd(&out[(size_t)d * D + i], __half2float(row[i]));
    }
}

// One warp per node: accumulate all bucketed messages in registers, then a
// single read-modify-write of the output row. No atomics, no contention.
__global__ __launch_bounds__(256) void aggregate(
    float* __restrict__ out, int N)
{
    int n = (blockIdx.x * 256 + threadIdx.x) >> 5;
    if (n >= N) return;
    int lane = threadIdx.x & 31;
    int cnt = g_cnt[n];
    if (cnt > CAP) cnt = CAP;
    if (cnt == 0) return;

    float4 acc = *(const float4*)&out[(size_t)n * D + lane * 4];
    const unsigned* bk = &g_bucket[(size_t)n * CAP];

#pragma unroll 4
    for (int j = 0; j < cnt; j++) {
        unsigned pack = __ldg(&bk[j]);
        int s = pack & 0xFFFFFF;
        int r = pack >> 24;
        const __half2* row = (const __half2*)&g_hrel[((size_t)r * N + (size_t)s) * D];
        __half2 h0 = row[lane * 2];
        __half2 h1 = row[lane * 2 + 1];
        float2 f0 = __half22float2(h0);
        float2 f1 = __half22float2(h1);
        acc.x += f0.x; acc.y += f0.y; acc.z += f1.x; acc.w += f1.y;
    }
    *(float4*)&out[(size_t)n * D + lane * 4] = acc;
}

extern "C" void kernel_launch(void* const* d_in, const int* in_sizes, int n_in,
                              void* d_out, int out_size) {
    const float* feat   = (const float*)d_in[0];
    const int*   src    = (const int*)d_in[1];
    const int*   dst    = (const int*)d_in[2];
    const int*   etypes = (const int*)d_in[3];
    const float* weight = (const float*)d_in[4];
    const float* loopw  = (const float*)d_in[5];
    const float* bias   = (const float*)d_in[6];
    float* out = (float*)d_out;

    int N = in_sizes[0] / D;
    int E = in_sizes[1];

    dim3 grid((N + BM - 1) / BM, 3);
    gemm_tc<<<grid, 256>>>(feat, weight, loopw, bias, out, N);

    bin_edges<<<(E + 255) / 256, 256>>>(src, dst, etypes, out, E, N);

    int agg_blocks = (N * 32 + 255) / 256;
    aggregate<<<agg_blocks, 256>>>(out, N);
}

// round 5
// speedup vs baseline: 1.6003x; 1.1895x over previous
#include <cuda_runtime.h>
#include <cuda_fp16.h>

#define D       128
#define NMAX    50000
#define CAP     64

#define BM 128
#define BK 32
#define ASTR 40    // A smem row stride in halfs (80B: 16B-aligned, ldmatrix conflict-free)
#define BSTR 136   // B smem row stride in halfs (272B: 16B-aligned, ldmatrix conflict-free)

// Scratch: pre-transformed pre-scaled per-relation node features (fp16),
// per-node edge counters, fixed-capacity edge buckets.
__device__ __half   g_hrel[2ull * NMAX * D];
__device__ int      g_cnt[NMAX];
__device__ unsigned g_bucket[(size_t)NMAX * CAP];

static __device__ __forceinline__ void ldsm_x4(
    unsigned& r0, unsigned& r1, unsigned& r2, unsigned& r3, unsigned addr)
{
    asm volatile("ldmatrix.sync.aligned.m8n8.x4.shared.b16 {%0,%1,%2,%3}, [%4];"
                 : "=r"(r0), "=r"(r1), "=r"(r2), "=r"(r3) : "r"(addr));
}

static __device__ __forceinline__ void ldsm_x4_t(
    unsigned& r0, unsigned& r1, unsigned& r2, unsigned& r3, unsigned addr)
{
    asm volatile("ldmatrix.sync.aligned.m8n8.x4.trans.shared.b16 {%0,%1,%2,%3}, [%4];"
                 : "=r"(r0), "=r"(r1), "=r"(r2), "=r"(r3) : "r"(addr));
}

static __device__ __forceinline__ void mma_f16(
    float c[4], const unsigned a[4], unsigned b0, unsigned b1)
{
    asm volatile(
        "mma.sync.aligned.m16n8k16.row.col.f32.f16.f16.f32 "
        "{%0,%1,%2,%3}, {%4,%5,%6,%7}, {%8,%9}, {%0,%1,%2,%3};"
        : "+f"(c[0]), "+f"(c[1]), "+f"(c[2]), "+f"(c[3])
        : "r"(a[0]), "r"(a[1]), "r"(a[2]), "r"(a[3]), "r"(b0), "r"(b1));
}

// Tensor-core GEMM (fp16 mma, fp32 accum), weight scaling fused into B load:
//   cb 0,1: h_rel[cb] = feat @ (s*W[cb])       (fp16 output)
//   cb 2:   out      = bias + feat @ (s*loopW) (fp32 output)
// cb==0 blocks also zero the per-node counters for the binning pass.
__global__ __launch_bounds__(256, 2) void gemm_tc(
    const float* __restrict__ feat,
    const float* __restrict__ weight,
    const float* __restrict__ loopw,
    const float* __restrict__ bias,
    float* __restrict__ out,
    int N)
{
    __shared__ __align__(16) __half As[2][BM][ASTR];  // [buf][m][k] row-major
    __shared__ __align__(16) __half Bs[2][BK][BSTR];  // [buf][k][n] row-major

    const int tid  = threadIdx.x;
    const int lane = tid & 31;
    const int wid  = tid >> 5;
    const int g    = lane >> 2;
    const int t    = lane & 3;
    const int wm   = (wid & 3) * 32;
    const int wn   = (wid >> 2) * 64;
    const int m0   = blockIdx.x * BM;
    const int cb   = blockIdx.y;

    if (cb == 0 && tid < BM) {
        int n = m0 + tid;
        if (n < N) g_cnt[n] = 0;
    }

    const float s = 0.70710678118654752440f;
    const float* B = (cb < 2) ? (weight + (size_t)cb * D * D) : loopw;

    // gmem load mapping
    const int arow = tid >> 1;              // 0..127
    const int koff = (tid & 1) * 16;        // 0 or 16
    const int gm_a = m0 + arow;
    const int brow = tid >> 3;              // 0..31
    const int bnoff = (tid & 7) * 16;       // 0..112

    // ldmatrix lane->address mapping
    const int a_m = lane & 15, a_k = (lane >> 4) * 8;
    const int b_k = lane & 15, b_n = (lane >> 4) * 8;
    const unsigned as_sz = BM * ASTR * 2;
    const unsigned bs_sz = BK * BSTR * 2;
    const unsigned as0 = (unsigned)__cvta_generic_to_shared(&As[0][wm + a_m][a_k]);
    const unsigned bs0 = (unsigned)__cvta_generic_to_shared(&Bs[0][b_k][wn + b_n]);

    float acc[2][8][4];
#pragma unroll
    for (int i = 0; i < 2; i++)
#pragma unroll
        for (int j = 0; j < 8; j++)
#pragma unroll
            for (int q = 0; q < 4; q++) acc[i][j][q] = 0.f;

    float4 ra[4], rb[4];

    // ---- prologue: load panel 0
#pragma unroll
    for (int i = 0; i < 4; i++) {
        ra[i] = make_float4(0.f, 0.f, 0.f, 0.f);
        if (gm_a < N) ra[i] = *(const float4*)&feat[(size_t)gm_a * D + koff + i * 4];
        rb[i] = *(const float4*)&B[(size_t)brow * D + bnoff + i * 4];
    }

    int buf = 0;
    {
        __half2 ha[8], hb[8];
#pragma unroll
        for (int i = 0; i < 4; i++) {
            ha[2 * i]     = __floats2half2_rn(ra[i].x, ra[i].y);
            ha[2 * i + 1] = __floats2half2_rn(ra[i].z, ra[i].w);
            hb[2 * i]     = __floats2half2_rn(s * rb[i].x, s * rb[i].y);
            hb[2 * i + 1] = __floats2half2_rn(s * rb[i].z, s * rb[i].w);
        }
        *(uint4*)&As[0][arow][koff]     = *(uint4*)&ha[0];
        *(uint4*)&As[0][arow][koff + 8] = *(uint4*)&ha[4];
        *(uint4*)&Bs[0][brow][bnoff]     = *(uint4*)&hb[0];
        *(uint4*)&Bs[0][brow][bnoff + 8] = *(uint4*)&hb[4];
    }
    __syncthreads();

#pragma unroll
    for (int p = 0; p < 4; p++) {
        int k_next = (p + 1) * BK;
        if (p < 3) {
#pragma unroll
            for (int i = 0; i < 4; i++) {
                ra[i] = make_float4(0.f, 0.f, 0.f, 0.f);
                if (gm_a < N) ra[i] = *(const float4*)&feat[(size_t)gm_a * D + k_next + koff + i * 4];
                rb[i] = *(const float4*)&B[(size_t)(k_next + brow) * D + bnoff + i * 4];
            }
        }

        unsigned as_b = as0 + buf * as_sz;
        unsigned bs_b = bs0 + buf * bs_sz;
#pragma unroll
        for (int kk = 0; kk < BK; kk += 16) {
            unsigned a[2][4];
            ldsm_x4(a[0][0], a[0][1], a[0][2], a[0][3], as_b + kk * 2);
            ldsm_x4(a[1][0], a[1][1], a[1][2], a[1][3], as_b + 16 * ASTR * 2 + kk * 2);
#pragma unroll
            for (int q = 0; q < 4; q++) {
                unsigned bq[4];
                ldsm_x4_t(bq[0], bq[1], bq[2], bq[3],
                          bs_b + kk * BSTR * 2 + q * 16 * 2);
                mma_f16(acc[0][2 * q],     a[0], bq[0], bq[1]);
                mma_f16(acc[1][2 * q],     a[1], bq[0], bq[1]);
                mma_f16(acc[0][2 * q + 1], a[0], bq[2], bq[3]);
                mma_f16(acc[1][2 * q + 1], a[1], bq[2], bq[3]);
            }
        }

        if (p < 3) {
            int nb2 = buf ^ 1;
            __half2 ha[8], hb[8];
#pragma unroll
            for (int i = 0; i < 4; i++) {
                ha[2 * i]     = __floats2half2_rn(ra[i].x, ra[i].y);
                ha[2 * i + 1] = __floats2half2_rn(ra[i].z, ra[i].w);
                hb[2 * i]     = __floats2half2_rn(s * rb[i].x, s * rb[i].y);
                hb[2 * i + 1] = __floats2half2_rn(s * rb[i].z, s * rb[i].w);
            }
            __syncthreads();
            *(uint4*)&As[nb2][arow][koff]     = *(uint4*)&ha[0];
            *(uint4*)&As[nb2][arow][koff + 8] = *(uint4*)&ha[4];
            *(uint4*)&Bs[nb2][brow][bnoff]     = *(uint4*)&hb[0];
            *(uint4*)&Bs[nb2][brow][bnoff + 8] = *(uint4*)&hb[4];
            __syncthreads();
            buf ^= 1;
        }
    }

    // ---- Epilogue: frag (c0,c1)@(g,2t), (c2,c3)@(g+8,2t)
#pragma unroll
    for (int mt = 0; mt < 2; mt++) {
        int gm_lo = m0 + wm + mt * 16 + g;
        int gm_hi = gm_lo + 8;
#pragma unroll
        for (int nt = 0; nt < 8; nt++) {
            int col = wn + nt * 8 + 2 * t;
            if (cb < 2) {
                __half* dstb = &g_hrel[(size_t)cb * N * D];
                if (gm_lo < N)
                    *(__half2*)&dstb[(size_t)gm_lo * D + col] =
                        __floats2half2_rn(acc[mt][nt][0], acc[mt][nt][1]);
                if (gm_hi < N)
                    *(__half2*)&dstb[(size_t)gm_hi * D + col] =
                        __floats2half2_rn(acc[mt][nt][2], acc[mt][nt][3]);
            } else {
                float2 bv = *(const float2*)&bias[col];
                if (gm_lo < N)
                    *(float2*)&out[(size_t)gm_lo * D + col] =
                        make_float2(acc[mt][nt][0] + bv.x, acc[mt][nt][1] + bv.y);
                if (gm_hi < N)
                    *(float2*)&out[(size_t)gm_hi * D + col] =
                        make_float2(acc[mt][nt][2] + bv.x, acc[mt][nt][3] + bv.y);
            }
        }
    }
}

// One thread per edge: append packed (rel<<24 | src) into dst's bucket.
// Overflow (probabilistically impossible at deg~Binomial(E,1/N), CAP=64)
// falls back to direct atomic accumulation, preserving correctness.
__global__ __launch_bounds__(256) void bin_edges(
    const int* __restrict__ src,
    const int* __restrict__ dst,
    const int* __restrict__ et,
    float* __restrict__ out,
    int E, int N)
{
    int e = blockIdx.x * blockDim.x + threadIdx.x;
    if (e >= E) return;
    int s = __ldg(&src[e]);
    int d = __ldg(&dst[e]);
    int r = __ldg(&et[e]);
    int pos = atomicAdd(&g_cnt[d], 1);
    if (pos < CAP) {
        g_bucket[(size_t)d * CAP + pos] = (unsigned)s | ((unsigned)r << 24);
    } else {
        const __half* row = &g_hrel[((size_t)r * N + (size_t)s) * D];
        for (int i = 0; i < D; i++)
            atomicAdd(&out[(size_t)d * D + i], __half2float(row[i]));
    }
}

// One warp per node: accumulate all bucketed messages in registers, then a
// single read-modify-write of the output row. No atomics, no contention.
__global__ __launch_bounds__(256) void aggregate(
    float* __restrict__ out, int N)
{
    int n = (blockIdx.x * 256 + threadIdx.x) >> 5;
    if (n >= N) return;
    int lane = threadIdx.x & 31;
    int cnt = g_cnt[n];
    if (cnt > CAP) cnt = CAP;
    if (cnt == 0) return;

    float4 acc = *(const float4*)&out[(size_t)n * D + lane * 4];
    const unsigned* bk = &g_bucket[(size_t)n * CAP];

#pragma unroll 4
    for (int j = 0; j < cnt; j++) {
        unsigned pack = __ldg(&bk[j]);
        int s = pack & 0xFFFFFF;
        int r = pack >> 24;
        const __half2* row = (const __half2*)&g_hrel[((size_t)r * N + (size_t)s) * D];
        __half2 h0 = row[lane * 2];
        __half2 h1 = row[lane * 2 + 1];
        float2 f0 = __half22float2(h0);
        float2 f1 = __half22float2(h1);
        acc.x += f0.x; acc.y += f0.y; acc.z += f1.x; acc.w += f1.y;
    }
    *(float4*)&out[(size_t)n * D + lane * 4] = acc;
}

extern "C" void kernel_launch(void* const* d_in, const int* in_sizes, int n_in,
                              void* d_out, int out_size) {
    const float* feat   = (const float*)d_in[0];
    const int*   src    = (const int*)d_in[1];
    const int*   dst    = (const int*)d_in[2];
    const int*   etypes = (const int*)d_in[3];
    const float* weight = (const float*)d_in[4];
    const float* loopw  = (const float*)d_in[5];
    const float* bias   = (const float*)d_in[6];
    float* out = (float*)d_out;

    int N = in_sizes[0] / D;
    int E = in_sizes[1];

    dim3 grid((N + BM - 1) / BM, 3);
    gemm_tc<<<grid, 256>>>(feat, weight, loopw, bias, out, N);

    bin_edges<<<(E + 255) / 256, 256>>>(src, dst, etypes, out, E, N);

    int agg_blocks = (N * 32 + 255) / 256;
    aggregate<<<agg_blocks, 256>>>(out, N);
}

// round 6
// speedup vs baseline: 1.7502x; 1.0937x over previous
#include <cuda_runtime.h>
#include <cuda_fp16.h>

#define D       128
#define NMAX    50000
#define CAP     64

#define BM 128
#define BN 64
#define BK 32
#define STAGES 3
#define ASTR 40    // A smem row stride (halfs): 80B -> ldmatrix conflict-free
#define BSTRB 72   // B smem row stride (halfs): 144B -> ldmatrix conflict-free

// Scratch: fp16 feat, fp16 pre-scaled weights [3][128][128], fp16 h_rel,
// per-node counters, edge buckets.
__device__ __half   g_feat16[(size_t)NMAX * D];
__device__ __half   g_w16[3 * D * D];
__device__ __half   g_hrel[2ull * NMAX * D];
__device__ int      g_cnt[NMAX];
__device__ unsigned g_bucket[(size_t)NMAX * CAP];

static __device__ __forceinline__ void cp16(unsigned d, const void* s, bool pred) {
    asm volatile("cp.async.cg.shared.global [%0], [%1], 16, %2;"
                 :: "r"(d), "l"(s), "r"(pred ? 16 : 0));
}
static __device__ __forceinline__ void cp_commit() {
    asm volatile("cp.async.commit_group;");
}
template <int NN> static __device__ __forceinline__ void cp_wait() {
    asm volatile("cp.async.wait_group %0;" :: "n"(NN));
}

static __device__ __forceinline__ void ldsm_x4(
    unsigned& r0, unsigned& r1, unsigned& r2, unsigned& r3, unsigned addr)
{
    asm volatile("ldmatrix.sync.aligned.m8n8.x4.shared.b16 {%0,%1,%2,%3}, [%4];"
                 : "=r"(r0), "=r"(r1), "=r"(r2), "=r"(r3) : "r"(addr));
}
static __device__ __forceinline__ void ldsm_x4_t(
    unsigned& r0, unsigned& r1, unsigned& r2, unsigned& r3, unsigned addr)
{
    asm volatile("ldmatrix.sync.aligned.m8n8.x4.trans.shared.b16 {%0,%1,%2,%3}, [%4];"
                 : "=r"(r0), "=r"(r1), "=r"(r2), "=r"(r3) : "r"(addr));
}
static __device__ __forceinline__ void mma_f16(
    float c[4], const unsigned a[4], unsigned b0, unsigned b1)
{
    asm volatile(
        "mma.sync.aligned.m16n8k16.row.col.f32.f16.f16.f32 "
        "{%0,%1,%2,%3}, {%4,%5,%6,%7}, {%8,%9}, {%0,%1,%2,%3};"
        : "+f"(c[0]), "+f"(c[1]), "+f"(c[2]), "+f"(c[3])
        : "r"(a[0]), "r"(a[1]), "r"(a[2]), "r"(a[3]), "r"(b0), "r"(b1));
}

// prep: feat -> fp16; weights -> pre-scaled fp16 [W0|W1|loopW]; zero counters.
__global__ __launch_bounds__(256) void prep(
    const float* __restrict__ feat,
    const float* __restrict__ weight,
    const float* __restrict__ loopw,
    int N)
{
    const float s = 0.70710678118654752440f;
    int idx = blockIdx.x * blockDim.x + threadIdx.x;
    int featChunks = N * D / 8;
    if (idx < featChunks) {
        float4 v0 = *(const float4*)&feat[(size_t)idx * 8];
        float4 v1 = *(const float4*)&feat[(size_t)idx * 8 + 4];
        __half2 h[4];
        h[0] = __floats2half2_rn(v0.x, v0.y);
        h[1] = __floats2half2_rn(v0.z, v0.w);
        h[2] = __floats2half2_rn(v1.x, v1.y);
        h[3] = __floats2half2_rn(v1.z, v1.w);
        *(uint4*)&g_feat16[(size_t)idx * 8] = *(uint4*)h;
    } else if (idx < featChunks + 3 * D * D / 8) {
        int j = idx - featChunks;                 // 0..6143
        const float* srcp = (j < 2 * D * D / 8)
            ? &weight[(size_t)j * 8]
            : &loopw[(size_t)(j - 2 * D * D / 8) * 8];
        float4 v0 = *(const float4*)srcp;
        float4 v1 = *(const float4*)(srcp + 4);
        __half2 h[4];
        h[0] = __floats2half2_rn(s * v0.x, s * v0.y);
        h[1] = __floats2half2_rn(s * v0.z, s * v0.w);
        h[2] = __floats2half2_rn(s * v1.x, s * v1.y);
        h[3] = __floats2half2_rn(s * v1.z, s * v1.w);
        *(uint4*)&g_w16[(size_t)j * 8] = *(uint4*)h;
    } else if (idx < featChunks + 3 * D * D / 8 + N) {
        g_cnt[idx - featChunks - 3 * D * D / 8] = 0;
    }
}

// fp16 tensor-core GEMM, 3-stage cp.async pipeline.
//   cb = blockIdx.y>>1 selects weight plane; (blockIdx.y&1) selects 64-col half.
//   cb 0,1: h_rel[cb] (fp16); cb 2: out = bias + loop message (fp32).
__global__ __launch_bounds__(256, 3) void gemm16(
    const float* __restrict__ bias,
    float* __restrict__ out,
    int N)
{
    __shared__ __align__(16) __half As[STAGES][BM][ASTR];   // [m][k]
    __shared__ __align__(16) __half Bs[STAGES][BK][BSTRB];  // [k][n]

    const int tid  = threadIdx.x;
    const int lane = tid & 31;
    const int wid  = tid >> 5;
    const int g    = lane >> 2;
    const int t    = lane & 3;
    const int wm   = (wid & 3) * 32;
    const int wn   = (wid >> 2) * 32;
    const int m0   = blockIdx.x * BM;
    const int cb   = blockIdx.y >> 1;
    const int n0   = (blockIdx.y & 1) * BN;

    const __half* Bg = g_w16 + (size_t)cb * D * D;

    // cp.async mapping
    const int arow = tid >> 1;                  // 0..127
    const int aoff = (tid & 1) * 16;            // halfs within k-panel
    const int gm_a = m0 + arow;
    const bool apred = gm_a < N;
    const int brow = tid >> 3;                  // 0..31
    const int boff = (tid & 7) * 8;             // halfs within BN

    const unsigned asA = (unsigned)__cvta_generic_to_shared(&As[0][arow][aoff]);
    const unsigned asB = (unsigned)__cvta_generic_to_shared(&Bs[0][brow][boff]);
    const unsigned aStage = BM * ASTR * 2;
    const unsigned bStage = BK * BSTRB * 2;

    // ldmatrix mapping
    const int a_m = lane & 15, a_k = (lane >> 4) * 8;
    const int b_k = lane & 15, b_n = (lane >> 4) * 8;
    const unsigned asL = (unsigned)__cvta_generic_to_shared(&As[0][wm + a_m][a_k]);
    const unsigned bsL = (unsigned)__cvta_generic_to_shared(&Bs[0][b_k][wn + b_n]);

    float acc[2][4][4];
#pragma unroll
    for (int i = 0; i < 2; i++)
#pragma unroll
        for (int j = 0; j < 4; j++)
#pragma unroll
            for (int q = 0; q < 4; q++) acc[i][j][q] = 0.f;

    auto issue = [&](int p, int st) {
        const __half* gA = &g_feat16[(size_t)gm_a * D + p * BK + aoff];
        cp16(asA + st * aStage, gA, apred);
        cp16(asA + st * aStage + 16, gA + 8, apred);
        const __half* gB = &Bg[(size_t)(p * BK + brow) * D + n0 + boff];
        cp16(asB + st * bStage, gB, true);
        cp_commit();
    };

    issue(0, 0);
    issue(1, 1);

#pragma unroll
    for (int p = 0; p < 4; p++) {
        if (p < 3) { cp_wait<1>(); } else { cp_wait<0>(); }
        __syncthreads();
        if (p < 2) issue(p + 2, (p + 2) % STAGES);

        const int st = p % STAGES;
        const unsigned aB = asL + st * aStage;
        const unsigned bB = bsL + st * bStage;
#pragma unroll
        for (int kk = 0; kk < BK; kk += 16) {
            unsigned a[2][4];
            ldsm_x4(a[0][0], a[0][1], a[0][2], a[0][3], aB + kk * 2);
            ldsm_x4(a[1][0], a[1][1], a[1][2], a[1][3], aB + 16 * ASTR * 2 + kk * 2);
#pragma unroll
            for (int q = 0; q < 2; q++) {
                unsigned bq[4];
                ldsm_x4_t(bq[0], bq[1], bq[2], bq[3],
                          bB + kk * BSTRB * 2 + q * 16 * 2);
                mma_f16(acc[0][2 * q],     a[0], bq[0], bq[1]);
                mma_f16(acc[1][2 * q],     a[1], bq[0], bq[1]);
                mma_f16(acc[0][2 * q + 1], a[0], bq[2], bq[3]);
                mma_f16(acc[1][2 * q + 1], a[1], bq[2], bq[3]);
            }
        }
    }

    // Epilogue: frag (c0,c1)@(g,2t), (c2,c3)@(g+8,2t)
#pragma unroll
    for (int mt = 0; mt < 2; mt++) {
        int gm_lo = m0 + wm + mt * 16 + g;
        int gm_hi = gm_lo + 8;
#pragma unroll
        for (int nt = 0; nt < 4; nt++) {
            int col = n0 + wn + nt * 8 + 2 * t;
            if (cb < 2) {
                __half* dstb = &g_hrel[(size_t)cb * N * D];
                if (gm_lo < N)
                    *(__half2*)&dstb[(size_t)gm_lo * D + col] =
                        __floats2half2_rn(acc[mt][nt][0], acc[mt][nt][1]);
                if (gm_hi < N)
                    *(__half2*)&dstb[(size_t)gm_hi * D + col] =
                        __floats2half2_rn(acc[mt][nt][2], acc[mt][nt][3]);
            } else {
                float2 bv = *(const float2*)&bias[col];
                if (gm_lo < N)
                    *(float2*)&out[(size_t)gm_lo * D + col] =
                        make_float2(acc[mt][nt][0] + bv.x, acc[mt][nt][1] + bv.y);
                if (gm_hi < N)
                    *(float2*)&out[(size_t)gm_hi * D + col] =
                        make_float2(acc[mt][nt][2] + bv.x, acc[mt][nt][3] + bv.y);
            }
        }
    }
}

// One thread per edge: append packed (rel<<24 | src) into dst's bucket.
// Overflow (probabilistically impossible, CAP=64) falls back to atomics.
__global__ __launch_bounds__(256) void bin_edges(
    const int* __restrict__ src,
    const int* __restrict__ dst,
    const int* __restrict__ et,
    float* __restrict__ out,
    int E, int N)
{
    int e = blockIdx.x * blockDim.x + threadIdx.x;
    if (e >= E) return;
    int s = __ldg(&src[e]);
    int d = __ldg(&dst[e]);
    int r = __ldg(&et[e]);
    int pos = atomicAdd(&g_cnt[d], 1);
    if (pos < CAP) {
        g_bucket[(size_t)d * CAP + pos] = (unsigned)s | ((unsigned)r << 24);
    } else {
        const __half* row = &g_hrel[((size_t)r * N + (size_t)s) * D];
        for (int i = 0; i < D; i++)
            atomicAdd(&out[(size_t)d * D + i], __half2float(row[i]));
    }
}

// One warp per node: accumulate bucketed messages in registers, single RMW
// of the output row. No atomics.
__global__ __launch_bounds__(256) void aggregate(
    float* __restrict__ out, int N)
{
    int n = (blockIdx.x * 256 + threadIdx.x) >> 5;
    if (n >= N) return;
    int lane = threadIdx.x & 31;
    int cnt = g_cnt[n];
    if (cnt > CAP) cnt = CAP;
    if (cnt == 0) return;

    float4 acc = *(const float4*)&out[(size_t)n * D + lane * 4];
    const unsigned* bk = &g_bucket[(size_t)n * CAP];

#pragma unroll 4
    for (int j = 0; j < cnt; j++) {
        unsigned pack = __ldg(&bk[j]);
        int s = pack & 0xFFFFFF;
        int r = pack >> 24;
        const __half2* row = (const __half2*)&g_hrel[((size_t)r * N + (size_t)s) * D];
        __half2 h0 = row[lane * 2];
        __half2 h1 = row[lane * 2 + 1];
        float2 f0 = __half22float2(h0);
        float2 f1 = __half22float2(h1);
        acc.x += f0.x; acc.y += f0.y; acc.z += f1.x; acc.w += f1.y;
    }
    *(float4*)&out[(size_t)n * D + lane * 4] = acc;
}

extern "C" void kernel_launch(void* const* d_in, const int* in_sizes, int n_in,
                              void* d_out, int out_size) {
    const float* feat   = (const float*)d_in[0];
    const int*   src    = (const int*)d_in[1];
    const int*   dst    = (const int*)d_in[2];
    const int*   etypes = (const int*)d_in[3];
    const float* weight = (const float*)d_in[4];
    const float* loopw  = (const float*)d_in[5];
    const float* bias   = (const float*)d_in[6];
    float* out = (float*)d_out;

    int N = in_sizes[0] / D;
    int E = in_sizes[1];

    int prepWork = N * D / 8 + 3 * D * D / 8 + N;
    prep<<<(prepWork + 255) / 256, 256>>>(feat, weight, loopw, N);

    dim3 grid((N + BM - 1) / BM, 6);
    gemm16<<<grid, 256>>>(bias, out, N);

    bin_edges<<<(E + 255) / 256, 256>>>(src, dst, etypes, out, E, N);

    int agg_blocks = (N * 32 + 255) / 256;
    aggregate<<<agg_blocks, 256>>>(out, N);
}

// round 7
// speedup vs baseline: 1.7543x; 1.0023x over previous
#include <cuda_runtime.h>
#include <cuda_fp16.h>

#define D       128
#define NMAX    50000
#define CAP     64

#define BM 128
#define BN 64
#define BK 32
#define STAGES 3
#define ASTR 40    // A smem row stride (halfs): 80B -> ldmatrix conflict-free
#define BSTRB 72   // B smem row stride (halfs): 144B -> ldmatrix conflict-free

// Scratch: fp16 feat, fp16 pre-scaled weights [3][128][128], fp16 h_rel,
// per-node counters, edge buckets.
__device__ __half   g_feat16[(size_t)NMAX * D];
__device__ __half   g_w16[3 * D * D];
__device__ __half   g_hrel[2ull * NMAX * D];
__device__ int      g_cnt[NMAX];
__device__ unsigned g_bucket[(size_t)NMAX * CAP];

static __device__ __forceinline__ void cp16(unsigned d, const void* s, bool pred) {
    asm volatile("cp.async.cg.shared.global [%0], [%1], 16, %2;"
                 :: "r"(d), "l"(s), "r"(pred ? 16 : 0));
}
static __device__ __forceinline__ void cp_commit() {
    asm volatile("cp.async.commit_group;");
}
template <int NN> static __device__ __forceinline__ void cp_wait() {
    asm volatile("cp.async.wait_group %0;" :: "n"(NN));
}

static __device__ __forceinline__ void ldsm_x4(
    unsigned& r0, unsigned& r1, unsigned& r2, unsigned& r3, unsigned addr)
{
    asm volatile("ldmatrix.sync.aligned.m8n8.x4.shared.b16 {%0,%1,%2,%3}, [%4];"
                 : "=r"(r0), "=r"(r1), "=r"(r2), "=r"(r3) : "r"(addr));
}
static __device__ __forceinline__ void ldsm_x4_t(
    unsigned& r0, unsigned& r1, unsigned& r2, unsigned& r3, unsigned addr)
{
    asm volatile("ldmatrix.sync.aligned.m8n8.x4.trans.shared.b16 {%0,%1,%2,%3}, [%4];"
                 : "=r"(r0), "=r"(r1), "=r"(r2), "=r"(r3) : "r"(addr));
}
static __device__ __forceinline__ void mma_f16(
    float c[4], const unsigned a[4], unsigned b0, unsigned b1)
{
    asm volatile(
        "mma.sync.aligned.m16n8k16.row.col.f32.f16.f16.f32 "
        "{%0,%1,%2,%3}, {%4,%5,%6,%7}, {%8,%9}, {%0,%1,%2,%3};"
        : "+f"(c[0]), "+f"(c[1]), "+f"(c[2]), "+f"(c[3])
        : "r"(a[0]), "r"(a[1]), "r"(a[2]), "r"(a[3]), "r"(b0), "r"(b1));
}

// prep: feat -> fp16; weights -> pre-scaled fp16 [W0|W1|loopW]; zero counters.
__global__ __launch_bounds__(256) void prep(
    const float* __restrict__ feat,
    const float* __restrict__ weight,
    const float* __restrict__ loopw,
    int N)
{
    const float s = 0.70710678118654752440f;
    int idx = blockIdx.x * blockDim.x + threadIdx.x;
    int featChunks = N * D / 8;
    if (idx < featChunks) {
        float4 v0 = *(const float4*)&feat[(size_t)idx * 8];
        float4 v1 = *(const float4*)&feat[(size_t)idx * 8 + 4];
        __half2 h[4];
        h[0] = __floats2half2_rn(v0.x, v0.y);
        h[1] = __floats2half2_rn(v0.z, v0.w);
        h[2] = __floats2half2_rn(v1.x, v1.y);
        h[3] = __floats2half2_rn(v1.z, v1.w);
        *(uint4*)&g_feat16[(size_t)idx * 8] = *(uint4*)h;
    } else if (idx < featChunks + 3 * D * D / 8) {
        int j = idx - featChunks;
        const float* srcp = (j < 2 * D * D / 8)
            ? &weight[(size_t)j * 8]
            : &loopw[(size_t)(j - 2 * D * D / 8) * 8];
        float4 v0 = *(const float4*)srcp;
        float4 v1 = *(const float4*)(srcp + 4);
        __half2 h[4];
        h[0] = __floats2half2_rn(s * v0.x, s * v0.y);
        h[1] = __floats2half2_rn(s * v0.z, s * v0.w);
        h[2] = __floats2half2_rn(s * v1.x, s * v1.y);
        h[3] = __floats2half2_rn(s * v1.z, s * v1.w);
        *(uint4*)&g_w16[(size_t)j * 8] = *(uint4*)h;
    } else if (idx < featChunks + 3 * D * D / 8 + N) {
        g_cnt[idx - featChunks - 3 * D * D / 8] = 0;
    }
}

// fp16 tensor-core GEMM, 3-stage cp.async pipeline.
//   cb = blockIdx.y>>1 selects weight plane; (blockIdx.y&1) selects 64-col half.
//   cb 0,1: h_rel[cb] (fp16); cb 2: out = bias + loop message (fp32).
__global__ __launch_bounds__(256, 3) void gemm16(
    const float* __restrict__ bias,
    float* __restrict__ out,
    int N)
{
    __shared__ __align__(16) __half As[STAGES][BM][ASTR];   // [m][k]
    __shared__ __align__(16) __half Bs[STAGES][BK][BSTRB];  // [k][n]

    const int tid  = threadIdx.x;
    const int lane = tid & 31;
    const int wid  = tid >> 5;
    const int g    = lane >> 2;
    const int t    = lane & 3;
    const int wm   = (wid & 3) * 32;
    const int wn   = (wid >> 2) * 32;
    const int m0   = blockIdx.x * BM;
    const int cb   = blockIdx.y >> 1;
    const int n0   = (blockIdx.y & 1) * BN;

    const __half* Bg = g_w16 + (size_t)cb * D * D;

    const int arow = tid >> 1;
    const int aoff = (tid & 1) * 16;
    const int gm_a = m0 + arow;
    const bool apred = gm_a < N;
    const int brow = tid >> 3;
    const int boff = (tid & 7) * 8;

    const unsigned asA = (unsigned)__cvta_generic_to_shared(&As[0][arow][aoff]);
    const unsigned asB = (unsigned)__cvta_generic_to_shared(&Bs[0][brow][boff]);
    const unsigned aStage = BM * ASTR * 2;
    const unsigned bStage = BK * BSTRB * 2;

    const int a_m = lane & 15, a_k = (lane >> 4) * 8;
    const int b_k = lane & 15, b_n = (lane >> 4) * 8;
    const unsigned asL = (unsigned)__cvta_generic_to_shared(&As[0][wm + a_m][a_k]);
    const unsigned bsL = (unsigned)__cvta_generic_to_shared(&Bs[0][b_k][wn + b_n]);

    float acc[2][4][4];
#pragma unroll
    for (int i = 0; i < 2; i++)
#pragma unroll
        for (int j = 0; j < 4; j++)
#pragma unroll
            for (int q = 0; q < 4; q++) acc[i][j][q] = 0.f;

    auto issue = [&](int p, int st) {
        const __half* gA = &g_feat16[(size_t)gm_a * D + p * BK + aoff];
        cp16(asA + st * aStage, gA, apred);
        cp16(asA + st * aStage + 16, gA + 8, apred);
        const __half* gB = &Bg[(size_t)(p * BK + brow) * D + n0 + boff];
        cp16(asB + st * bStage, gB, true);
        cp_commit();
    };

    issue(0, 0);
    issue(1, 1);

#pragma unroll
    for (int p = 0; p < 4; p++) {
        if (p < 3) { cp_wait<1>(); } else { cp_wait<0>(); }
        __syncthreads();
        if (p < 2) issue(p + 2, (p + 2) % STAGES);

        const int st = p % STAGES;
        const unsigned aB = asL + st * aStage;
        const unsigned bB = bsL + st * bStage;
#pragma unroll
        for (int kk = 0; kk < BK; kk += 16) {
            unsigned a[2][4];
            ldsm_x4(a[0][0], a[0][1], a[0][2], a[0][3], aB + kk * 2);
            ldsm_x4(a[1][0], a[1][1], a[1][2], a[1][3], aB + 16 * ASTR * 2 + kk * 2);
#pragma unroll
            for (int q = 0; q < 2; q++) {
                unsigned bq[4];
                ldsm_x4_t(bq[0], bq[1], bq[2], bq[3],
                          bB + kk * BSTRB * 2 + q * 16 * 2);
                mma_f16(acc[0][2 * q],     a[0], bq[0], bq[1]);
                mma_f16(acc[1][2 * q],     a[1], bq[0], bq[1]);
                mma_f16(acc[0][2 * q + 1], a[0], bq[2], bq[3]);
                mma_f16(acc[1][2 * q + 1], a[1], bq[2], bq[3]);
            }
        }
    }

    // Epilogue: frag (c0,c1)@(g,2t), (c2,c3)@(g+8,2t)
#pragma unroll
    for (int mt = 0; mt < 2; mt++) {
        int gm_lo = m0 + wm + mt * 16 + g;
        int gm_hi = gm_lo + 8;
#pragma unroll
        for (int nt = 0; nt < 4; nt++) {
            int col = n0 + wn + nt * 8 + 2 * t;
            if (cb < 2) {
                __half* dstb = &g_hrel[(size_t)cb * N * D];
                if (gm_lo < N)
                    *(__half2*)&dstb[(size_t)gm_lo * D + col] =
                        __floats2half2_rn(acc[mt][nt][0], acc[mt][nt][1]);
                if (gm_hi < N)
                    *(__half2*)&dstb[(size_t)gm_hi * D + col] =
                        __floats2half2_rn(acc[mt][nt][2], acc[mt][nt][3]);
            } else {
                float2 bv = *(const float2*)&bias[col];
                if (gm_lo < N)
                    *(float2*)&out[(size_t)gm_lo * D + col] =
                        make_float2(acc[mt][nt][0] + bv.x, acc[mt][nt][1] + bv.y);
                if (gm_hi < N)
                    *(float2*)&out[(size_t)gm_hi * D + col] =
                        make_float2(acc[mt][nt][2] + bv.x, acc[mt][nt][3] + bv.y);
            }
        }
    }
}

// One thread per edge: append the precomputed h_rel plane-row index
// (r*N + src) into dst's bucket. Overflow (probabilistically impossible,
// CAP=64) falls back to direct atomic accumulation.
__global__ __launch_bounds__(256) void bin_edges(
    const int* __restrict__ src,
    const int* __restrict__ dst,
    const int* __restrict__ et,
    float* __restrict__ out,
    int E, int N)
{
    int e = blockIdx.x * blockDim.x + threadIdx.x;
    if (e >= E) return;
    int s = __ldg(&src[e]);
    int d = __ldg(&dst[e]);
    int r = __ldg(&et[e]);
    int pos = atomicAdd(&g_cnt[d], 1);
    if (pos < CAP) {
        g_bucket[(size_t)d * CAP + pos] = (unsigned)(r * N + s);
    } else {
        const __half* row = &g_hrel[((size_t)r * N + (size_t)s) * D];
        for (int i = 0; i < D; i++)
            atomicAdd(&out[(size_t)d * D + i], __half2float(row[i]));
    }
}

// One warp per node: accumulate bucketed messages in registers, single RMW
// of the output row. No atomics. Gather = one LDG.64 per entry per lane.
__global__ __launch_bounds__(256) void aggregate(
    float* __restrict__ out, int N)
{
    int n = (blockIdx.x * 256 + threadIdx.x) >> 5;
    if (n >= N) return;
    int lane = threadIdx.x & 31;
    int cnt = g_cnt[n];
    if (cnt > CAP) cnt = CAP;
    if (cnt == 0) return;

    float4 acc = *(const float4*)&out[(size_t)n * D + lane * 4];
    const unsigned* bk = &g_bucket[(size_t)n * CAP];

#pragma unroll 8
    for (int j = 0; j < cnt; j++) {
        unsigned idx = __ldg(&bk[j]);
        const uint2* row = (const uint2*)&g_hrel[(size_t)idx * D];
        uint2 hv = __ldg(&row[lane]);
        float2 f0 = __half22float2(*(__half2*)&hv.x);
        float2 f1 = __half22float2(*(__half2*)&hv.y);
        acc.x += f0.x; acc.y += f0.y; acc.z += f1.x; acc.w += f1.y;
    }
    *(float4*)&out[(size_t)n * D + lane * 4] = acc;
}

extern "C" void kernel_launch(void* const* d_in, const int* in_sizes, int n_in,
                              void* d_out, int out_size) {
    const float* feat   = (const float*)d_in[0];
    const int*   src    = (const int*)d_in[1];
    const int*   dst    = (const int*)d_in[2];
    const int*   etypes = (const int*)d_in[3];
    const float* weight = (const float*)d_in[4];
    const float* loopw  = (const float*)d_in[5];
    const float* bias   = (const float*)d_in[6];
    float* out = (float*)d_out;

    int N = in_sizes[0] / D;
    int E = in_sizes[1];

    int prepWork = N * D / 8 + 3 * D * D / 8 + N;
    prep<<<(prepWork + 255) / 256, 256>>>(feat, weight, loopw, N);

    dim3 grid((N + BM - 1) / BM, 6);
    gemm16<<<grid, 256>>>(bias, out, N);

    bin_edges<<<(E + 255) / 256, 256>>>(src, dst, etypes, out, E, N);

    int agg_blocks = (N * 32 + 255) / 256;
    aggregate<<<agg_blocks, 256>>>(out, N);
}